// round 16
// baseline (speedup 1.0000x reference)
#include <cuda_runtime.h>
#include <math_constants.h>

// Shapes (fixed): x: [B=32, C=256, H=128, W=128] float32
#define B_   32
#define C_   256
#define HW_  16384   // 128*128
#define HW4_ 4096    // HW/4 (float4 groups)

#define XN_BLOCKS 512    // 32 b * 16 blocks/b
#define ENTRO_BLOCKS 64
#define HIST_BLOCKS  64

// Scratch (device globals — no allocation allowed; zero-initialized at load)
__device__ float g_pooled[B_ * C_];      // 32 KB
__device__ float g_xn[B_ * HW_];         // 2 MB
__device__ float g_ssum[XN_BLOCKS];      // sigmoid partials
__device__ float g_entro[HW_];           // 64 KB
__device__ float g_mm[ENTRO_BLOCKS * 2]; // per-block (min,max)
__device__ int   g_hist[256];
__device__ int   g_done[B_];             // pool blocks finished for batch b

__device__ __forceinline__ void gds() {
#if defined(__CUDA_ARCH__) && (__CUDA_ARCH__ >= 900)
    cudaGridDependencySynchronize();
#endif
}

// ---------------------------------------------------------------------------
// K1: pooled[b,c] = mean over HW. One block per (b,c), batch-major order so
//     batch b's 256 blocks are contiguous (b = blockIdx>>8). Each block
//     fences + bumps g_done[b] so k_xn can start on batch b immediately.
// ---------------------------------------------------------------------------
__global__ void __launch_bounds__(256) k_pool(const float* __restrict__ x) {
    const int tid = threadIdx.x;
    const int bc  = blockIdx.x;              // b*256 + c
    const int b   = bc >> 8;

    const float4* __restrict__ p =
        reinterpret_cast<const float4*>(x) + (size_t)bc * HW4_;

    float s0 = 0.f, s1 = 0.f, s2 = 0.f, s3 = 0.f;
    float s4 = 0.f, s5 = 0.f, s6 = 0.f, s7 = 0.f;
#pragma unroll
    for (int i = 0; i < 2; i++) {
        float4 a = p[tid + (8 * i + 0) * 256];
        float4 bb = p[tid + (8 * i + 1) * 256];
        float4 c = p[tid + (8 * i + 2) * 256];
        float4 d = p[tid + (8 * i + 3) * 256];
        float4 e = p[tid + (8 * i + 4) * 256];
        float4 f = p[tid + (8 * i + 5) * 256];
        float4 g = p[tid + (8 * i + 6) * 256];
        float4 h = p[tid + (8 * i + 7) * 256];
        s0 += (a.x + a.y) + (a.z + a.w);
        s1 += (bb.x + bb.y) + (bb.z + bb.w);
        s2 += (c.x + c.y) + (c.z + c.w);
        s3 += (d.x + d.y) + (d.z + d.w);
        s4 += (e.x + e.y) + (e.z + e.w);
        s5 += (f.x + f.y) + (f.z + f.w);
        s6 += (g.x + g.y) + (g.z + g.w);
        s7 += (h.x + h.y) + (h.z + h.w);
    }
    float s = (((s0 + s1) + (s2 + s3)) + ((s4 + s5) + (s6 + s7)));
#pragma unroll
    for (int o = 16; o > 0; o >>= 1)
        s += __shfl_down_sync(0xffffffffu, s, o);

    __shared__ float sw[8];
    if ((tid & 31) == 0) sw[tid >> 5] = s;
    __syncthreads();
    if (tid == 0) {
        float t = ((sw[0] + sw[1]) + (sw[2] + sw[3]))
                + ((sw[4] + sw[5]) + (sw[6] + sw[7]));
        g_pooled[bc] = t * (1.0f / (float)HW_);
        __threadfence();                       // release pooled[bc]
        atomicAdd(&g_done[b], 1);              // signal this channel done
    }
}

// ---------------------------------------------------------------------------
// K2: xn[b,sp] = (1/C) * sum_c x[b,c,sp] * pooled[b,c]
//     Launched with PSS (no gds): each block spin-waits only on ITS batch's
//     256 pool flags, so xn overlaps pool's tail and reads L2-warm data.
// ---------------------------------------------------------------------------
__global__ void __launch_bounds__(256) k_xn(const float* __restrict__ x) {
    const int b   = blockIdx.x >> 4;                        // 0..31
    const int grp = ((blockIdx.x & 15) << 8) + threadIdx.x; // 0..4095

    if (threadIdx.x == 0) {
        while (atomicAdd(&g_done[b], 0) < C_) __nanosleep(64);
        __threadfence();                       // acquire pooled writes
    }
    __syncthreads();

    __shared__ float pw[C_];
    pw[threadIdx.x] = g_pooled[b * C_ + threadIdx.x];
    __syncthreads();

    const float4* __restrict__ xp =
        reinterpret_cast<const float4*>(x) + (size_t)b * C_ * HW4_ + grp;

    float ax = 0.0f, ay = 0.0f, az = 0.0f, aw = 0.0f;
#pragma unroll 16
    for (int c = 0; c < C_; c++) {
        float4 v = xp[(size_t)c * HW4_];
        float w = pw[c];
        ax = fmaf(v.x, w, ax);
        ay = fmaf(v.y, w, ay);
        az = fmaf(v.z, w, az);
        aw = fmaf(v.w, w, aw);
    }
    const float inv = 1.0f / (float)C_;
    float4 xn;
    xn.x = ax * inv; xn.y = ay * inv; xn.z = az * inv; xn.w = aw * inv;
    reinterpret_cast<float4*>(g_xn)[(size_t)b * HW4_ + grp] = xn;

    float sg = 1.0f / (1.0f + __expf(-xn.x))
             + 1.0f / (1.0f + __expf(-xn.y))
             + 1.0f / (1.0f + __expf(-xn.z))
             + 1.0f / (1.0f + __expf(-xn.w));
#pragma unroll
    for (int o = 16; o > 0; o >>= 1)
        sg += __shfl_down_sync(0xffffffffu, sg, o);

    __shared__ float sw[8];
    if ((threadIdx.x & 31) == 0) sw[threadIdx.x >> 5] = sg;
    __syncthreads();
    if (threadIdx.x == 0) {
        float t = ((sw[0] + sw[1]) + (sw[2] + sw[3]))
                + ((sw[4] + sw[5]) + (sw[6] + sw[7]));
        g_ssum[blockIdx.x] = t;
    }
}

// ---------------------------------------------------------------------------
// K3: entro[sp] = mean over b of xn[b,sp]; per-block min/max partials.
//     Block 0 also resets g_done + zeroes g_hist for the NEXT graph replay /
//     the k_hist that follows (gds edge guarantees visibility).
// ---------------------------------------------------------------------------
__global__ void __launch_bounds__(256) k_entro() {
    gds();   // wait for k_xn completion (g_xn visible; pool flags consumed)

    if (blockIdx.x == 0) {
        g_hist[threadIdx.x] = 0;
        if (threadIdx.x < B_) g_done[threadIdx.x] = 0;
    }

    const int sp = blockIdx.x * 256 + threadIdx.x;
    float a = 0.0f;
#pragma unroll
    for (int b = 0; b < B_; b++) a += g_xn[(size_t)b * HW_ + sp];
    float v = a * (1.0f / (float)B_);
    g_entro[sp] = v;

    __shared__ float smin[256], smax[256];
    smin[threadIdx.x] = v;
    smax[threadIdx.x] = v;
    __syncthreads();
#pragma unroll
    for (int o = 128; o > 0; o >>= 1) {
        if (threadIdx.x < o) {
            smin[threadIdx.x] = fminf(smin[threadIdx.x], smin[threadIdx.x + o]);
            smax[threadIdx.x] = fmaxf(smax[threadIdx.x], smax[threadIdx.x + o]);
        }
        __syncthreads();
    }
    if (threadIdx.x == 0) {
        g_mm[blockIdx.x * 2 + 0] = smin[0];
        g_mm[blockIdx.x * 2 + 1] = smax[0];
    }
}

// ---------------------------------------------------------------------------
// K4: 64 blocks: reduce min/max partials (redundant, cheap), bin 256 entro
//     elements each into shared histogram, flush to global histogram.
// ---------------------------------------------------------------------------
__global__ void __launch_bounds__(256) k_hist() {
    gds();   // wait for k_entro's g_entro / g_mm / g_hist-zero writes

    const int tid = threadIdx.x;

    __shared__ float smin[64], smax[64];
    __shared__ int hist[256];
    hist[tid] = 0;
    if (tid < 64) {
        smin[tid] = g_mm[tid * 2 + 0];
        smax[tid] = g_mm[tid * 2 + 1];
    }
    __syncthreads();
#pragma unroll
    for (int o = 32; o > 0; o >>= 1) {
        if (tid < o) {
            smin[tid] = fminf(smin[tid], smin[tid + o]);
            smax[tid] = fmaxf(smax[tid], smax[tid + o]);
        }
        __syncthreads();
    }
    const float emin = smin[0];
    const float denom = smax[0] - emin;

    float e = (g_entro[blockIdx.x * 256 + tid] - emin) / denom * 255.0f;
    int bin = (int)floorf(e * (256.0f / 255.0f));
    bin = min(max(bin, 0), 255);
    atomicAdd(&hist[bin], 1);
    __syncthreads();

    if (hist[tid] != 0) atomicAdd(&g_hist[tid], hist[tid]);
}

// ---------------------------------------------------------------------------
// K5: entropy over 256 bins + nz, sigmoid-sum reduce (512 partials), output.
// ---------------------------------------------------------------------------
__global__ void __launch_bounds__(256) k_out(float* __restrict__ out) {
    gds();   // wait for k_hist's g_hist writes

    const int tid = threadIdx.x;

    __shared__ double sd[256];
    sd[tid] = (double)g_ssum[tid] + (double)g_ssum[tid + 256];
    __syncthreads();
#pragma unroll
    for (int o = 128; o > 0; o >>= 1) {
        if (tid < o) sd[tid] += sd[tid + o];
        __syncthreads();
    }

    __shared__ float ssum[256];
    __shared__ int   snz[256];
    int h = g_hist[tid];
    float hisv = (float)h * (1.0f / (float)HW_);
    ssum[tid] = hisv * (-logf(hisv + 1e-8f));
    snz[tid]  = (h != 0) ? 1 : 0;
    __syncthreads();
#pragma unroll
    for (int o = 128; o > 0; o >>= 1) {
        if (tid < o) {
            ssum[tid] += ssum[tid + o];
            snz[tid]  += snz[tid + o];
        }
        __syncthreads();
    }

    if (tid == 0) {
        float s = (float)(sd[0] / (double)((size_t)B_ * HW_));
        float entro_final = ssum[0] / (float)snz[0];
        out[0] = s + entro_final * 10.0f;
    }
}

// ---------------------------------------------------------------------------
// Launch: k_pool normally; downstream via PDL/PSS. k_xn carries no gds — its
// per-batch spin flags let it overlap k_pool's tail.
// ---------------------------------------------------------------------------
static inline void launch_pdl(void* func, dim3 grid, dim3 block,
                              void** args) {
    cudaLaunchConfig_t cfg = {};
    cfg.gridDim  = grid;
    cfg.blockDim = block;
    cfg.dynamicSmemBytes = 0;
    cfg.stream = 0;   // legacy default stream (same as <<<>>>)
    cudaLaunchAttribute attr[1];
    attr[0].id = cudaLaunchAttributeProgrammaticStreamSerialization;
    attr[0].val.programmaticStreamSerializationAllowed = 1;
    cfg.attrs = attr;
    cfg.numAttrs = 1;
    cudaLaunchKernelExC(&cfg, func, args);
}

extern "C" void kernel_launch(void* const* d_in, const int* in_sizes, int n_in,
                              void* d_out, int out_size) {
    const float* x = (const float*)d_in[0];
    float* out = (float*)d_out;

    k_pool<<<B_ * C_, 256>>>(x);

    {   // k_xn(x) — overlaps pool via per-batch flags
        void* args[] = { (void*)&x };
        launch_pdl((void*)k_xn, dim3(XN_BLOCKS), dim3(256), args);
    }
    {   // k_entro()
        launch_pdl((void*)k_entro, dim3(ENTRO_BLOCKS), dim3(256), nullptr);
    }
    {   // k_hist()
        launch_pdl((void*)k_hist, dim3(HIST_BLOCKS), dim3(256), nullptr);
    }
    {   // k_out(out)
        void* args[] = { (void*)&out };
        launch_pdl((void*)k_out, dim3(1), dim3(256), args);
    }
}